// round 5
// baseline (speedup 1.0000x reference)
#include <cuda_runtime.h>
#include <cuda_bf16.h>
#include <math.h>
#include <stdint.h>

#define BATCH 2
#define SEQ   4096
#define DIM   1024

#define NQ  ((size_t)BATCH * SEQ * DIM)   // 8M elems
#define NP  ((size_t)BATCH * SEQ * SEQ)   // 33.5M elems
#define NW  ((size_t)DIM * DIM)

// ---- device scratch (pre-split bf16 hi/lo) ----
__device__ __nv_bfloat16 g_xh[NQ],  g_xl[NQ];
__device__ __nv_bfloat16 g_W3h[3 * NW], g_W3l[3 * NW];   // Wq|Wk|Wv stacked
__device__ __nv_bfloat16 g_Woh[NW], g_Wol[NW];
__device__ __nv_bfloat16 g_QKVh[3 * NQ], g_QKVl[3 * NQ]; // Q|K|V stacked
__device__ __nv_bfloat16 g_Oh[NQ],  g_Ol[NQ];
__device__ float         g_S[NP];
__device__ __nv_bfloat16 g_Ph[NP],  g_Pl[NP];

// ---------------------------------------------------------------------------
// PTX helpers
// ---------------------------------------------------------------------------
__device__ __forceinline__ uint32_t cvta_s(const void* p) {
    return (uint32_t)__cvta_generic_to_shared(p);
}
__device__ __forceinline__ void cp16(uint32_t dst, const void* src) {
    asm volatile("cp.async.cg.shared.global [%0], [%1], 16;" :: "r"(dst), "l"(src));
}
__device__ __forceinline__ void ldmx4(uint32_t* r, uint32_t a) {
    asm volatile("ldmatrix.sync.aligned.m8n8.x4.shared.b16 {%0,%1,%2,%3}, [%4];"
                 : "=r"(r[0]), "=r"(r[1]), "=r"(r[2]), "=r"(r[3]) : "r"(a));
}
__device__ __forceinline__ void ldmx4t(uint32_t* r, uint32_t a) {
    asm volatile("ldmatrix.sync.aligned.m8n8.x4.trans.shared.b16 {%0,%1,%2,%3}, [%4];"
                 : "=r"(r[0]), "=r"(r[1]), "=r"(r[2]), "=r"(r[3]) : "r"(a));
}
__device__ __forceinline__ void mma16816(float* c, const uint32_t* a, const uint32_t* b) {
    asm volatile(
        "mma.sync.aligned.m16n8k16.row.col.f32.bf16.bf16.f32 "
        "{%0,%1,%2,%3}, {%4,%5,%6,%7}, {%8,%9}, {%0,%1,%2,%3};"
        : "+f"(c[0]), "+f"(c[1]), "+f"(c[2]), "+f"(c[3])
        : "r"(a[0]), "r"(a[1]), "r"(a[2]), "r"(a[3]), "r"(b[0]), "r"(b[1]));
}
__device__ __forceinline__ __nv_bfloat162 hi2(float a, float b) {
    __nv_bfloat162 r; r.x = __float2bfloat16(a); r.y = __float2bfloat16(b); return r;
}
__device__ __forceinline__ __nv_bfloat162 lo2(float a, float b, __nv_bfloat162 h) {
    __nv_bfloat162 r;
    r.x = __float2bfloat16(a - __bfloat162float(h.x));
    r.y = __float2bfloat16(b - __bfloat162float(h.y));
    return r;
}

// ---------------------------------------------------------------------------
// Split-bf16 (3x mma) GEMM, 256x128 CTA tile, BK=32, 512 threads (warps 4x4),
// 2-stage cp.async. C = alpha * A @ op(B) + bias[z].
//   A [M,K] rm hi/lo. TRANSB ? B [N,K] : B [K,N] hi/lo.
// ---------------------------------------------------------------------------
constexpr int LDA = 40;

template <bool TRANSB>
__device__ __forceinline__ void load_stage5(
    __nv_bfloat16* sb,
    const __nv_bfloat16* Ah, const __nv_bfloat16* Al,
    const __nv_bfloat16* Bh, const __nv_bfloat16* Bl,
    int k0, int K, int N, int tid)
{
    constexpr int AE = 256 * LDA;                 // 10240
    constexpr int BE = TRANSB ? 128 * LDA : 32 * 136;
    __nv_bfloat16* sAh = sb;
    __nv_bfloat16* sAl = sb + AE;
    __nv_bfloat16* sBh = sb + 2 * AE;
    __nv_bfloat16* sBl = sb + 2 * AE + BE;

    // A: 256x32 = 1024 cp16 per matrix, 2 per thread
#pragma unroll
    for (int i = 0; i < 2; i++) {
        int c = tid + (i << 9);
        int row = c >> 2, col = (c & 3) << 3;
        size_t g = (size_t)row * K + k0 + col;
        uint32_t so = row * LDA + col;
        cp16(cvta_s(sAh + so), Ah + g);
        cp16(cvta_s(sAl + so), Al + g);
    }
    if (TRANSB) {
        // B: 128x32 = 512 cp16 per matrix, 1 per thread
        int row = tid >> 2, col = (tid & 3) << 3;
        size_t g = (size_t)row * K + k0 + col;
        uint32_t so = row * LDA + col;
        cp16(cvta_s(sBh + so), Bh + g);
        cp16(cvta_s(sBl + so), Bl + g);
    } else {
        // B: 32x128 = 512 cp16 per matrix, 1 per thread
        int row = tid >> 4, col = (tid & 15) << 3;
        size_t g = (size_t)(k0 + row) * N + col;
        uint32_t so = row * 136 + col;
        cp16(cvta_s(sBh + so), Bh + g);
        cp16(cvta_s(sBl + so), Bl + g);
    }
    asm volatile("cp.async.commit_group;");
}

template <bool TRANSB, bool SPLIT_OUT>
__global__ __launch_bounds__(512, 1)
void gemm5(const __nv_bfloat16* __restrict__ Agh, const __nv_bfloat16* __restrict__ Agl,
           const __nv_bfloat16* __restrict__ Bgh, const __nv_bfloat16* __restrict__ Bgl,
           float* __restrict__ Cf,
           __nv_bfloat16* __restrict__ Ch, __nv_bfloat16* __restrict__ Cl,
           const float* __restrict__ b0, const float* __restrict__ b1,
           const float* __restrict__ b2,
           int N, int K, float alpha,
           size_t sA, size_t sB, size_t sC)
{
    extern __shared__ __align__(16) char smraw[];
    __nv_bfloat16* sm = (__nv_bfloat16*)smraw;
    constexpr int AE    = 256 * LDA;
    constexpr int BE    = TRANSB ? 128 * LDA : 32 * 136;
    constexpr int STAGE = 2 * AE + 2 * BE;        // elems
    constexpr int LDB   = TRANSB ? LDA : 136;

    const int tid  = threadIdx.x;
    const int lane = tid & 31;
    const int warp = tid >> 5;
    const int wm   = warp & 3;      // 4 row groups of 64
    const int wn   = warp >> 2;     // 4 col groups of 32
    const int z    = blockIdx.z;
    const int bm = blockIdx.y << 8, bn = blockIdx.x << 7;

    const float* bias = (z == 0) ? b0 : (z == 1) ? b1 : b2;

    const __nv_bfloat16* Abh = Agh + z * sA + (size_t)bm * K;
    const __nv_bfloat16* Abl = Agl + z * sA + (size_t)bm * K;
    const __nv_bfloat16 *Bbh, *Bbl;
    if (TRANSB) {
        Bbh = Bgh + z * sB + (size_t)bn * K;
        Bbl = Bgl + z * sB + (size_t)bn * K;
    } else {
        Bbh = Bgh + z * sB + bn;
        Bbl = Bgl + z * sB + bn;
    }

    float acc[4][4][4];
#pragma unroll
    for (int i = 0; i < 4; i++)
#pragma unroll
        for (int j = 0; j < 4; j++)
#pragma unroll
            for (int l = 0; l < 4; l++) acc[i][j][l] = 0.f;

    const int lm_r = lane & 15;
    const int lm_c = (lane >> 4) << 3;
    const int tr_k = (lane & 7) | (((lane >> 3) & 1) << 3);
    const int tr_n = (lane >> 4) << 3;

    load_stage5<TRANSB>(sm, Abh, Abl, Bbh, Bbl, 0, K, N, tid);

    const int nT = K >> 5;
    for (int kt = 0; kt < nT; kt++) {
        asm volatile("cp.async.wait_group 0;");
        __syncthreads();
        if (kt + 1 < nT)
            load_stage5<TRANSB>(sm + ((kt + 1) & 1) * STAGE, Abh, Abl, Bbh, Bbl,
                                (kt + 1) << 5, K, N, tid);

        __nv_bfloat16* cs  = sm + (kt & 1) * STAGE;
        __nv_bfloat16* sAh = cs;
        __nv_bfloat16* sAl = cs + AE;
        __nv_bfloat16* sBh = cs + 2 * AE;
        __nv_bfloat16* sBl = cs + 2 * AE + BE;

#pragma unroll
        for (int ks = 0; ks < 2; ks++) {
            uint32_t af[4][4], bh[4][2], bl[4][2];

            if (TRANSB) {
#pragma unroll
                for (int h = 0; h < 2; h++) {
                    int row = wn * 32 + h * 16 + lm_r;
                    int col = ks * 16 + lm_c;
                    uint32_t t[4];
                    ldmx4(t, cvta_s(&sBh[row * LDB + col]));
                    bh[2 * h][0] = t[0]; bh[2 * h][1] = t[2];
                    bh[2 * h + 1][0] = t[1]; bh[2 * h + 1][1] = t[3];
                    ldmx4(t, cvta_s(&sBl[row * LDB + col]));
                    bl[2 * h][0] = t[0]; bl[2 * h][1] = t[2];
                    bl[2 * h + 1][0] = t[1]; bl[2 * h + 1][1] = t[3];
                }
            } else {
                int krow = ks * 16 + tr_k;
#pragma unroll
                for (int h = 0; h < 2; h++) {
                    int col = wn * 32 + h * 16 + tr_n;
                    uint32_t t[4];
                    ldmx4t(t, cvta_s(&sBh[krow * LDB + col]));
                    bh[2 * h][0] = t[0]; bh[2 * h][1] = t[1];
                    bh[2 * h + 1][0] = t[2]; bh[2 * h + 1][1] = t[3];
                    ldmx4t(t, cvta_s(&sBl[krow * LDB + col]));
                    bl[2 * h][0] = t[0]; bl[2 * h][1] = t[1];
                    bl[2 * h + 1][0] = t[2]; bl[2 * h + 1][1] = t[3];
                }
            }

            // A hi: hi*hi + hi*lo
#pragma unroll
            for (int mf = 0; mf < 4; mf++) {
                int row = wm * 64 + mf * 16 + lm_r;
                ldmx4(af[mf], cvta_s(&sAh[row * LDA + ks * 16 + lm_c]));
            }
#pragma unroll
            for (int mf = 0; mf < 4; mf++)
#pragma unroll
                for (int nf = 0; nf < 4; nf++) {
                    mma16816(acc[mf][nf], af[mf], bh[nf]);
                    mma16816(acc[mf][nf], af[mf], bl[nf]);
                }
            // A lo: lo*hi
#pragma unroll
            for (int mf = 0; mf < 4; mf++) {
                int row = wm * 64 + mf * 16 + lm_r;
                ldmx4(af[mf], cvta_s(&sAl[row * LDA + ks * 16 + lm_c]));
            }
#pragma unroll
            for (int mf = 0; mf < 4; mf++)
#pragma unroll
                for (int nf = 0; nf < 4; nf++)
                    mma16816(acc[mf][nf], af[mf], bh[nf]);
        }
        __syncthreads();
    }

    // ---- epilogue
    const int g  = lane >> 2;
    const int t2 = (lane & 3) << 1;
#pragma unroll
    for (int mf = 0; mf < 4; mf++) {
        int r0 = wm * 64 + mf * 16 + g;
#pragma unroll
        for (int nf = 0; nf < 4; nf++) {
            int c = wn * 32 + nf * 8 + t2;
            float bb0 = 0.f, bb1 = 0.f;
            if (bias) { bb0 = bias[bn + c]; bb1 = bias[bn + c + 1]; }
            float v00 = acc[mf][nf][0] * alpha + bb0;
            float v01 = acc[mf][nf][1] * alpha + bb1;
            float v10 = acc[mf][nf][2] * alpha + bb0;
            float v11 = acc[mf][nf][3] * alpha + bb1;
            if (SPLIT_OUT) {
                __nv_bfloat16* Chb = Ch + z * sC + (size_t)bm * N + bn;
                __nv_bfloat16* Clb = Cl + z * sC + (size_t)bm * N + bn;
                __nv_bfloat162 h0 = hi2(v00, v01), h1 = hi2(v10, v11);
                __nv_bfloat162 L0 = lo2(v00, v01, h0), L1 = lo2(v10, v11, h1);
                *(__nv_bfloat162*)(Chb + (size_t)r0 * N + c)       = h0;
                *(__nv_bfloat162*)(Chb + (size_t)(r0 + 8) * N + c) = h1;
                *(__nv_bfloat162*)(Clb + (size_t)r0 * N + c)       = L0;
                *(__nv_bfloat162*)(Clb + (size_t)(r0 + 8) * N + c) = L1;
            } else {
                float* Cfb = Cf + z * sC + (size_t)bm * N + bn;
                *(float2*)(Cfb + (size_t)r0 * N + c)       = make_float2(v00, v01);
                *(float2*)(Cfb + (size_t)(r0 + 8) * N + c) = make_float2(v10, v11);
            }
        }
    }
}

// ---------------------------------------------------------------------------
// elementwise fp32 -> (bf16 hi, bf16 lo)
// ---------------------------------------------------------------------------
__global__ __launch_bounds__(256)
void split_f32(const float* __restrict__ x, __nv_bfloat16* __restrict__ h,
               __nv_bfloat16* __restrict__ l, int n4)
{
    int i = blockIdx.x * blockDim.x + threadIdx.x;
    if (i >= n4) return;
    float4 v = ((const float4*)x)[i];
    __nv_bfloat162 h0 = hi2(v.x, v.y), h1 = hi2(v.z, v.w);
    __nv_bfloat162 l0 = lo2(v.x, v.y, h0), l1 = lo2(v.z, v.w, h1);
    ((__nv_bfloat162*)h)[2 * i]     = h0;
    ((__nv_bfloat162*)h)[2 * i + 1] = h1;
    ((__nv_bfloat162*)l)[2 * i]     = l0;
    ((__nv_bfloat162*)l)[2 * i + 1] = l1;
}

// ---------------------------------------------------------------------------
// Row softmax over 4096 fp32, writes bf16 hi/lo probs. 1 block / row.
// ---------------------------------------------------------------------------
__global__ __launch_bounds__(256)
void softmax_split(const float* __restrict__ S,
                   __nv_bfloat16* __restrict__ Ph, __nv_bfloat16* __restrict__ Pl)
{
    const float* row = S + (size_t)blockIdx.x * SEQ;
    __nv_bfloat16* rh = Ph + (size_t)blockIdx.x * SEQ;
    __nv_bfloat16* rl = Pl + (size_t)blockIdx.x * SEQ;
    const int tid = threadIdx.x;

    float v[16];
#pragma unroll
    for (int i = 0; i < 4; i++) {
        float4 t = *(const float4*)(row + i * 1024 + tid * 4);
        v[i * 4 + 0] = t.x; v[i * 4 + 1] = t.y;
        v[i * 4 + 2] = t.z; v[i * 4 + 3] = t.w;
    }
    __shared__ float sh[8];

    float m = -1e30f;
#pragma unroll
    for (int i = 0; i < 16; i++) m = fmaxf(m, v[i]);
#pragma unroll
    for (int o = 16; o > 0; o >>= 1) m = fmaxf(m, __shfl_xor_sync(0xffffffffu, m, o));
    if ((tid & 31) == 0) sh[tid >> 5] = m;
    __syncthreads();
    {
        float t = sh[tid & 7];
#pragma unroll
        for (int o = 4; o > 0; o >>= 1) t = fmaxf(t, __shfl_xor_sync(0xffffffffu, t, o));
        m = t;
    }
    __syncthreads();

    float s = 0.f;
#pragma unroll
    for (int i = 0; i < 16; i++) { v[i] = __expf(v[i] - m); s += v[i]; }
#pragma unroll
    for (int o = 16; o > 0; o >>= 1) s += __shfl_xor_sync(0xffffffffu, s, o);
    if ((tid & 31) == 0) sh[tid >> 5] = s;
    __syncthreads();
    {
        float t = sh[tid & 7];
#pragma unroll
        for (int o = 4; o > 0; o >>= 1) t += __shfl_xor_sync(0xffffffffu, t, o);
        s = t;
    }
    const float inv = 1.f / s;
#pragma unroll
    for (int i = 0; i < 4; i++) {
        float a = v[i * 4 + 0] * inv, b = v[i * 4 + 1] * inv;
        float c = v[i * 4 + 2] * inv, d = v[i * 4 + 3] * inv;
        __nv_bfloat162 h0 = hi2(a, b), h1 = hi2(c, d);
        __nv_bfloat162 l0 = lo2(a, b, h0), l1 = lo2(c, d, h1);
        int off = i * 1024 + tid * 4;
        *(__nv_bfloat162*)(rh + off)     = h0;
        *(__nv_bfloat162*)(rh + off + 2) = h1;
        *(__nv_bfloat162*)(rl + off)     = l0;
        *(__nv_bfloat162*)(rl + off + 2) = l1;
    }
}

// ---------------------------------------------------------------------------
// kernel_launch
// ---------------------------------------------------------------------------
extern "C" void kernel_launch(void* const* d_in, const int* in_sizes, int n_in,
                              void* d_out, int out_size)
{
    const float* x  = (const float*)d_in[0];
    const float* Wq = (const float*)d_in[1];
    const float* bq = (const float*)d_in[2];
    const float* Wk = (const float*)d_in[3];
    const float* bk = (const float*)d_in[4];
    const float* Wv = (const float*)d_in[5];
    const float* bv = (const float*)d_in[6];
    const float* Wo = (const float*)d_in[7];
    const float* bo = (const float*)d_in[8];
    float* out = (float*)d_out;

    __nv_bfloat16 *xh, *xl, *W3h, *W3l, *Woh, *Wol, *QKVh, *QKVl, *Oh, *Ol, *Ph, *Pl;
    float* S;
    cudaGetSymbolAddress((void**)&xh, g_xh);     cudaGetSymbolAddress((void**)&xl, g_xl);
    cudaGetSymbolAddress((void**)&W3h, g_W3h);   cudaGetSymbolAddress((void**)&W3l, g_W3l);
    cudaGetSymbolAddress((void**)&Woh, g_Woh);   cudaGetSymbolAddress((void**)&Wol, g_Wol);
    cudaGetSymbolAddress((void**)&QKVh, g_QKVh); cudaGetSymbolAddress((void**)&QKVl, g_QKVl);
    cudaGetSymbolAddress((void**)&Oh, g_Oh);     cudaGetSymbolAddress((void**)&Ol, g_Ol);
    cudaGetSymbolAddress((void**)&Ph, g_Ph);     cudaGetSymbolAddress((void**)&Pl, g_Pl);
    cudaGetSymbolAddress((void**)&S, g_S);

    // dynamic smem: elems*2B, 2 stages
    const int SM_T  = 2 * (2 * 256 * LDA + 2 * 128 * LDA) * 2;  // 122880
    const int SM_NN = 2 * (2 * 256 * LDA + 2 * 32 * 136) * 2;   // 116736
    cudaFuncSetAttribute(gemm5<false, true>,  cudaFuncAttributeMaxDynamicSharedMemorySize, SM_NN);
    cudaFuncSetAttribute(gemm5<false, false>, cudaFuncAttributeMaxDynamicSharedMemorySize, SM_NN);
    cudaFuncSetAttribute(gemm5<true,  false>, cudaFuncAttributeMaxDynamicSharedMemorySize, SM_T);

    const int M = BATCH * SEQ;          // 8192
    const float scale = 0.125f;         // 1/sqrt(64)
    dim3 b256(256), b512(512);

    const size_t sQ = (size_t)SEQ * DIM;

    // pre-split inputs (W's stacked q|k|v)
    split_f32<<<(int)(NQ / 4 + 255) / 256, b256>>>(x, xh, xl, (int)(NQ / 4));
    split_f32<<<(int)(NW / 4 + 255) / 256, b256>>>(Wq, W3h,          W3l,          (int)(NW / 4));
    split_f32<<<(int)(NW / 4 + 255) / 256, b256>>>(Wk, W3h + NW,     W3l + NW,     (int)(NW / 4));
    split_f32<<<(int)(NW / 4 + 255) / 256, b256>>>(Wv, W3h + 2 * NW, W3l + 2 * NW, (int)(NW / 4));
    split_f32<<<(int)(NW / 4 + 255) / 256, b256>>>(Wo, Woh, Wol, (int)(NW / 4));

    // fused QKV projection: z in {0,1,2} picks weight/bias/output slice
    dim3 gProj(DIM / 128, M / 256, 3);
    gemm5<false, true><<<gProj, b512, SM_NN>>>(xh, xl, W3h, W3l, nullptr,
                                               QKVh, QKVl, bq, bk, bv,
                                               DIM, DIM, 1.f, 0, NW, NQ);

    __nv_bfloat16 *Qh = QKVh,          *Ql = QKVl;
    __nv_bfloat16 *Kh = QKVh + NQ,     *Kl = QKVl + NQ;
    __nv_bfloat16 *Vh = QKVh + 2 * NQ, *Vl = QKVl + 2 * NQ;

    // scores: S = scale * Q @ K^T  (z = batch)
    dim3 gScore(SEQ / 128, SEQ / 256, BATCH);
    gemm5<true, false><<<gScore, b512, SM_T>>>(Qh, Ql, Kh, Kl, S, nullptr, nullptr,
                                               nullptr, nullptr, nullptr,
                                               SEQ, DIM, scale,
                                               sQ, sQ, (size_t)SEQ * SEQ);

    softmax_split<<<BATCH * SEQ, b256>>>(S, Ph, Pl);

    // O = P @ V  (z = batch)
    dim3 gPV(DIM / 128, SEQ / 256, BATCH);
    gemm5<false, true><<<gPV, b512, SM_NN>>>(Ph, Pl, Vh, Vl, nullptr, Oh, Ol,
                                             nullptr, nullptr, nullptr,
                                             DIM, SEQ, 1.f,
                                             (size_t)SEQ * SEQ, sQ, sQ);

    // out = O @ Wo + bo
    dim3 gOut(DIM / 128, M / 256, 1);
    gemm5<false, false><<<gOut, b512, SM_NN>>>(Oh, Ol, Woh, Wol, out, nullptr, nullptr,
                                               bo, bo, bo,
                                               DIM, DIM, 1.f, 0, 0, 0);
}

// round 6
// speedup vs baseline: 1.0097x; 1.0097x over previous
#include <cuda_runtime.h>
#include <cuda_bf16.h>
#include <math.h>
#include <stdint.h>

#define BATCH 2
#define SEQ   4096
#define DIM   1024

#define NQ  ((size_t)BATCH * SEQ * DIM)
#define NP  ((size_t)BATCH * SEQ * SEQ)
#define NW  ((size_t)DIM * DIM)

// ---- device scratch (pre-split bf16 hi/lo) ----
__device__ __nv_bfloat16 g_xh[NQ],  g_xl[NQ];
__device__ __nv_bfloat16 g_W3h[3 * NW], g_W3l[3 * NW];   // Wq|Wk|Wv stacked
__device__ __nv_bfloat16 g_Woh[NW], g_Wol[NW];
__device__ __nv_bfloat16 g_QKVh[3 * NQ], g_QKVl[3 * NQ]; // Q|K|V stacked
__device__ __nv_bfloat16 g_Oh[NQ],  g_Ol[NQ];
__device__ float         g_S[NP];
__device__ __nv_bfloat16 g_Ph[NP],  g_Pl[NP];

// ---------------------------------------------------------------------------
// PTX helpers
// ---------------------------------------------------------------------------
__device__ __forceinline__ uint32_t cvta_s(const void* p) {
    return (uint32_t)__cvta_generic_to_shared(p);
}
__device__ __forceinline__ void cp16(uint32_t dst, const void* src) {
    asm volatile("cp.async.cg.shared.global [%0], [%1], 16;" :: "r"(dst), "l"(src));
}
__device__ __forceinline__ void ldmx4(uint32_t* r, uint32_t a) {
    asm volatile("ldmatrix.sync.aligned.m8n8.x4.shared.b16 {%0,%1,%2,%3}, [%4];"
                 : "=r"(r[0]), "=r"(r[1]), "=r"(r[2]), "=r"(r[3]) : "r"(a));
}
__device__ __forceinline__ void ldmx4t(uint32_t* r, uint32_t a) {
    asm volatile("ldmatrix.sync.aligned.m8n8.x4.trans.shared.b16 {%0,%1,%2,%3}, [%4];"
                 : "=r"(r[0]), "=r"(r[1]), "=r"(r[2]), "=r"(r[3]) : "r"(a));
}
__device__ __forceinline__ void mma16816(float* c, const uint32_t* a, const uint32_t* b) {
    asm volatile(
        "mma.sync.aligned.m16n8k16.row.col.f32.bf16.bf16.f32 "
        "{%0,%1,%2,%3}, {%4,%5,%6,%7}, {%8,%9}, {%0,%1,%2,%3};"
        : "+f"(c[0]), "+f"(c[1]), "+f"(c[2]), "+f"(c[3])
        : "r"(a[0]), "r"(a[1]), "r"(a[2]), "r"(a[3]), "r"(b[0]), "r"(b[1]));
}
__device__ __forceinline__ __nv_bfloat162 hi2(float a, float b) {
    __nv_bfloat162 r; r.x = __float2bfloat16(a); r.y = __float2bfloat16(b); return r;
}
__device__ __forceinline__ __nv_bfloat162 lo2(float a, float b, __nv_bfloat162 h) {
    __nv_bfloat162 r;
    r.x = __float2bfloat16(a - __bfloat162float(h.x));
    r.y = __float2bfloat16(b - __bfloat162float(h.y));
    return r;
}

// ---------------------------------------------------------------------------
// Split-bf16 (3x mma) GEMM. CTA tile 128x256, BK=32, 256 threads,
// 8 warps (2 row-groups x 4 col-groups), warp tile 64x64.
// C = alpha * A @ op(B) + bias[z].  A [M,K] hi/lo.  TRANSB ? B [N,K] : B [K,N].
// ---------------------------------------------------------------------------
constexpr int LDA = 40;    // 32 + 8 pad (bf16 elems)
constexpr int LDN = 264;   // 256 + 8 pad (NN B tile rows)

template <bool TRANSB>
__device__ __forceinline__ void load_stage6(
    __nv_bfloat16* sb,
    const __nv_bfloat16* Ah, const __nv_bfloat16* Al,
    const __nv_bfloat16* Bh, const __nv_bfloat16* Bl,
    int k0, int K, int N, int tid)
{
    constexpr int AE = 128 * LDA;                    // 5120
    constexpr int BE = TRANSB ? 256 * LDA : 32 * LDN;
    __nv_bfloat16* sAh = sb;
    __nv_bfloat16* sAl = sb + AE;
    __nv_bfloat16* sBh = sb + 2 * AE;
    __nv_bfloat16* sBl = sb + 2 * AE + BE;

    // A: 128x32 -> 512 cp16 per matrix, 2 per thread
#pragma unroll
    for (int i = 0; i < 2; i++) {
        int c = tid + (i << 8);
        int row = c >> 2, col = (c & 3) << 3;
        size_t g = (size_t)row * K + k0 + col;
        uint32_t so = row * LDA + col;
        cp16(cvta_s(sAh + so), Ah + g);
        cp16(cvta_s(sAl + so), Al + g);
    }
    if (TRANSB) {
        // B: 256x32 -> 1024 cp16 per matrix, 4 per thread
#pragma unroll
        for (int i = 0; i < 4; i++) {
            int c = tid + (i << 8);
            int row = c >> 2, col = (c & 3) << 3;
            size_t g = (size_t)row * K + k0 + col;
            uint32_t so = row * LDA + col;
            cp16(cvta_s(sBh + so), Bh + g);
            cp16(cvta_s(sBl + so), Bl + g);
        }
    } else {
        // B: 32x256 -> 1024 cp16 per matrix, 4 per thread
#pragma unroll
        for (int i = 0; i < 4; i++) {
            int c = tid + (i << 8);
            int row = c >> 5, col = (c & 31) << 3;
            size_t g = (size_t)(k0 + row) * N + col;
            uint32_t so = row * LDN + col;
            cp16(cvta_s(sBh + so), Bh + g);
            cp16(cvta_s(sBl + so), Bl + g);
        }
    }
    asm volatile("cp.async.commit_group;");
}

template <bool TRANSB, bool SPLIT_OUT>
__global__ __launch_bounds__(256, 1)
void gemm6(const __nv_bfloat16* __restrict__ Agh, const __nv_bfloat16* __restrict__ Agl,
           const __nv_bfloat16* __restrict__ Bgh, const __nv_bfloat16* __restrict__ Bgl,
           float* __restrict__ Cf,
           __nv_bfloat16* __restrict__ Ch, __nv_bfloat16* __restrict__ Cl,
           const float* __restrict__ b0, const float* __restrict__ b1,
           const float* __restrict__ b2,
           int N, int K, float alpha,
           size_t sA, size_t sB, size_t sC)
{
    extern __shared__ __align__(16) char smraw[];
    __nv_bfloat16* sm = (__nv_bfloat16*)smraw;
    constexpr int AE    = 128 * LDA;
    constexpr int BE    = TRANSB ? 256 * LDA : 32 * LDN;
    constexpr int STAGE = 2 * AE + 2 * BE;
    constexpr int LDB   = TRANSB ? LDA : LDN;

    const int tid  = threadIdx.x;
    const int lane = tid & 31;
    const int warp = tid >> 5;
    const int wm   = warp & 1;      // 2 row groups of 64
    const int wn   = warp >> 1;     // 4 col groups of 64
    const int z    = blockIdx.z;
    const int bm = blockIdx.y << 7, bn = blockIdx.x << 8;

    const float* bias = (z == 0) ? b0 : (z == 1) ? b1 : b2;

    const __nv_bfloat16* Abh = Agh + z * sA + (size_t)bm * K;
    const __nv_bfloat16* Abl = Agl + z * sA + (size_t)bm * K;
    const __nv_bfloat16 *Bbh, *Bbl;
    if (TRANSB) {
        Bbh = Bgh + z * sB + (size_t)bn * K;
        Bbl = Bgl + z * sB + (size_t)bn * K;
    } else {
        Bbh = Bgh + z * sB + bn;
        Bbl = Bgl + z * sB + bn;
    }

    float acc[4][8][4];
#pragma unroll
    for (int i = 0; i < 4; i++)
#pragma unroll
        for (int j = 0; j < 8; j++)
#pragma unroll
            for (int l = 0; l < 4; l++) acc[i][j][l] = 0.f;

    const int lm_r = lane & 15;
    const int lm_c = (lane >> 4) << 3;
    const int tr_k = (lane & 7) | (((lane >> 3) & 1) << 3);
    const int tr_n = (lane >> 4) << 3;

    load_stage6<TRANSB>(sm, Abh, Abl, Bbh, Bbl, 0, K, N, tid);

    const int nT = K >> 5;
    for (int kt = 0; kt < nT; kt++) {
        asm volatile("cp.async.wait_group 0;");
        __syncthreads();
        if (kt + 1 < nT)
            load_stage6<TRANSB>(sm + ((kt + 1) & 1) * STAGE, Abh, Abl, Bbh, Bbl,
                                (kt + 1) << 5, K, N, tid);

        __nv_bfloat16* cs  = sm + (kt & 1) * STAGE;
        __nv_bfloat16* sAh = cs;
        __nv_bfloat16* sAl = cs + AE;
        __nv_bfloat16* sBh = cs + 2 * AE;
        __nv_bfloat16* sBl = cs + 2 * AE + BE;

#pragma unroll
        for (int ks = 0; ks < 2; ks++) {
            uint32_t af[4][4], bh[8][2], bl[8][2];

            // ---- B fragments: 64 cols (hi and lo)
            if (TRANSB) {
#pragma unroll
                for (int h = 0; h < 4; h++) {
                    int row = wn * 64 + h * 16 + lm_r;
                    int col = ks * 16 + lm_c;
                    uint32_t t[4];
                    ldmx4(t, cvta_s(&sBh[row * LDB + col]));
                    bh[2 * h][0] = t[0]; bh[2 * h][1] = t[2];
                    bh[2 * h + 1][0] = t[1]; bh[2 * h + 1][1] = t[3];
                    ldmx4(t, cvta_s(&sBl[row * LDB + col]));
                    bl[2 * h][0] = t[0]; bl[2 * h][1] = t[2];
                    bl[2 * h + 1][0] = t[1]; bl[2 * h + 1][1] = t[3];
                }
            } else {
                int krow = ks * 16 + tr_k;
#pragma unroll
                for (int h = 0; h < 4; h++) {
                    int col = wn * 64 + h * 16 + tr_n;
                    uint32_t t[4];
                    ldmx4t(t, cvta_s(&sBh[krow * LDB + col]));
                    bh[2 * h][0] = t[0]; bh[2 * h][1] = t[1];
                    bh[2 * h + 1][0] = t[2]; bh[2 * h + 1][1] = t[3];
                    ldmx4t(t, cvta_s(&sBl[krow * LDB + col]));
                    bl[2 * h][0] = t[0]; bl[2 * h][1] = t[1];
                    bl[2 * h + 1][0] = t[2]; bl[2 * h + 1][1] = t[3];
                }
            }

            // ---- A hi: hi*hi + hi*lo
#pragma unroll
            for (int mf = 0; mf < 4; mf++) {
                int row = wm * 64 + mf * 16 + lm_r;
                ldmx4(af[mf], cvta_s(&sAh[row * LDA + ks * 16 + lm_c]));
            }
#pragma unroll
            for (int mf = 0; mf < 4; mf++)
#pragma unroll
                for (int nf = 0; nf < 8; nf++) {
                    mma16816(acc[mf][nf], af[mf], bh[nf]);
                    mma16816(acc[mf][nf], af[mf], bl[nf]);
                }
            // ---- A lo: lo*hi
#pragma unroll
            for (int mf = 0; mf < 4; mf++) {
                int row = wm * 64 + mf * 16 + lm_r;
                ldmx4(af[mf], cvta_s(&sAl[row * LDA + ks * 16 + lm_c]));
            }
#pragma unroll
            for (int mf = 0; mf < 4; mf++)
#pragma unroll
                for (int nf = 0; nf < 8; nf++)
                    mma16816(acc[mf][nf], af[mf], bh[nf]);
        }
    }

    // ---- epilogue
    const int g  = lane >> 2;
    const int t2 = (lane & 3) << 1;
#pragma unroll
    for (int mf = 0; mf < 4; mf++) {
        int r0 = wm * 64 + mf * 16 + g;
#pragma unroll
        for (int nf = 0; nf < 8; nf++) {
            int c = wn * 64 + nf * 8 + t2;
            float bb0 = 0.f, bb1 = 0.f;
            if (bias) { bb0 = bias[bn + c]; bb1 = bias[bn + c + 1]; }
            float v00 = acc[mf][nf][0] * alpha + bb0;
            float v01 = acc[mf][nf][1] * alpha + bb1;
            float v10 = acc[mf][nf][2] * alpha + bb0;
            float v11 = acc[mf][nf][3] * alpha + bb1;
            if (SPLIT_OUT) {
                __nv_bfloat16* Chb = Ch + z * sC + (size_t)bm * N + bn;
                __nv_bfloat16* Clb = Cl + z * sC + (size_t)bm * N + bn;
                __nv_bfloat162 h0 = hi2(v00, v01), h1 = hi2(v10, v11);
                __nv_bfloat162 L0 = lo2(v00, v01, h0), L1 = lo2(v10, v11, h1);
                *(__nv_bfloat162*)(Chb + (size_t)r0 * N + c)       = h0;
                *(__nv_bfloat162*)(Chb + (size_t)(r0 + 8) * N + c) = h1;
                *(__nv_bfloat162*)(Clb + (size_t)r0 * N + c)       = L0;
                *(__nv_bfloat162*)(Clb + (size_t)(r0 + 8) * N + c) = L1;
            } else {
                float* Cfb = Cf + z * sC + (size_t)bm * N + bn;
                *(float2*)(Cfb + (size_t)r0 * N + c)       = make_float2(v00, v01);
                *(float2*)(Cfb + (size_t)(r0 + 8) * N + c) = make_float2(v10, v11);
            }
        }
    }
}

// ---------------------------------------------------------------------------
// elementwise fp32 -> (bf16 hi, bf16 lo)
// ---------------------------------------------------------------------------
__global__ __launch_bounds__(256)
void split_f32(const float* __restrict__ x, __nv_bfloat16* __restrict__ h,
               __nv_bfloat16* __restrict__ l, int n4)
{
    int i = blockIdx.x * blockDim.x + threadIdx.x;
    if (i >= n4) return;
    float4 v = ((const float4*)x)[i];
    __nv_bfloat162 h0 = hi2(v.x, v.y), h1 = hi2(v.z, v.w);
    __nv_bfloat162 l0 = lo2(v.x, v.y, h0), l1 = lo2(v.z, v.w, h1);
    ((__nv_bfloat162*)h)[2 * i]     = h0;
    ((__nv_bfloat162*)h)[2 * i + 1] = h1;
    ((__nv_bfloat162*)l)[2 * i]     = l0;
    ((__nv_bfloat162*)l)[2 * i + 1] = l1;
}

// ---------------------------------------------------------------------------
// Row softmax over 4096 fp32, writes bf16 hi/lo probs. 1 block / row.
// ---------------------------------------------------------------------------
__global__ __launch_bounds__(256)
void softmax_split(const float* __restrict__ S,
                   __nv_bfloat16* __restrict__ Ph, __nv_bfloat16* __restrict__ Pl)
{
    const float* row = S + (size_t)blockIdx.x * SEQ;
    __nv_bfloat16* rh = Ph + (size_t)blockIdx.x * SEQ;
    __nv_bfloat16* rl = Pl + (size_t)blockIdx.x * SEQ;
    const int tid = threadIdx.x;

    float v[16];
#pragma unroll
    for (int i = 0; i < 4; i++) {
        float4 t = *(const float4*)(row + i * 1024 + tid * 4);
        v[i * 4 + 0] = t.x; v[i * 4 + 1] = t.y;
        v[i * 4 + 2] = t.z; v[i * 4 + 3] = t.w;
    }
    __shared__ float sh[8];

    float m = -1e30f;
#pragma unroll
    for (int i = 0; i < 16; i++) m = fmaxf(m, v[i]);
#pragma unroll
    for (int o = 16; o > 0; o >>= 1) m = fmaxf(m, __shfl_xor_sync(0xffffffffu, m, o));
    if ((tid & 31) == 0) sh[tid >> 5] = m;
    __syncthreads();
    {
        float t = sh[tid & 7];
#pragma unroll
        for (int o = 4; o > 0; o >>= 1) t = fmaxf(t, __shfl_xor_sync(0xffffffffu, t, o));
        m = t;
    }
    __syncthreads();

    float s = 0.f;
#pragma unroll
    for (int i = 0; i < 16; i++) { v[i] = __expf(v[i] - m); s += v[i]; }
#pragma unroll
    for (int o = 16; o > 0; o >>= 1) s += __shfl_xor_sync(0xffffffffu, s, o);
    if ((tid & 31) == 0) sh[tid >> 5] = s;
    __syncthreads();
    {
        float t = sh[tid & 7];
#pragma unroll
        for (int o = 4; o > 0; o >>= 1) t += __shfl_xor_sync(0xffffffffu, t, o);
        s = t;
    }
    const float inv = 1.f / s;
#pragma unroll
    for (int i = 0; i < 4; i++) {
        float a = v[i * 4 + 0] * inv, b = v[i * 4 + 1] * inv;
        float c = v[i * 4 + 2] * inv, d = v[i * 4 + 3] * inv;
        __nv_bfloat162 h0 = hi2(a, b), h1 = hi2(c, d);
        __nv_bfloat162 l0 = lo2(a, b, h0), l1 = lo2(c, d, h1);
        int off = i * 1024 + tid * 4;
        *(__nv_bfloat162*)(rh + off)     = h0;
        *(__nv_bfloat162*)(rh + off + 2) = h1;
        *(__nv_bfloat162*)(rl + off)     = l0;
        *(__nv_bfloat162*)(rl + off + 2) = l1;
    }
}

// ---------------------------------------------------------------------------
// kernel_launch
// ---------------------------------------------------------------------------
extern "C" void kernel_launch(void* const* d_in, const int* in_sizes, int n_in,
                              void* d_out, int out_size)
{
    const float* x  = (const float*)d_in[0];
    const float* Wq = (const float*)d_in[1];
    const float* bq = (const float*)d_in[2];
    const float* Wk = (const float*)d_in[3];
    const float* bk = (const float*)d_in[4];
    const float* Wv = (const float*)d_in[5];
    const float* bv = (const float*)d_in[6];
    const float* Wo = (const float*)d_in[7];
    const float* bo = (const float*)d_in[8];
    float* out = (float*)d_out;

    __nv_bfloat16 *xh, *xl, *W3h, *W3l, *Woh, *Wol, *QKVh, *QKVl, *Oh, *Ol, *Ph, *Pl;
    float* S;
    cudaGetSymbolAddress((void**)&xh, g_xh);     cudaGetSymbolAddress((void**)&xl, g_xl);
    cudaGetSymbolAddress((void**)&W3h, g_W3h);   cudaGetSymbolAddress((void**)&W3l, g_W3l);
    cudaGetSymbolAddress((void**)&Woh, g_Woh);   cudaGetSymbolAddress((void**)&Wol, g_Wol);
    cudaGetSymbolAddress((void**)&QKVh, g_QKVh); cudaGetSymbolAddress((void**)&QKVl, g_QKVl);
    cudaGetSymbolAddress((void**)&Oh, g_Oh);     cudaGetSymbolAddress((void**)&Ol, g_Ol);
    cudaGetSymbolAddress((void**)&Ph, g_Ph);     cudaGetSymbolAddress((void**)&Pl, g_Pl);
    cudaGetSymbolAddress((void**)&S, g_S);

    // dynamic smem bytes (2 stages)
    const int SM_T  = 2 * 2 * (2 * 128 * LDA + 2 * 256 * LDA);   // 122880
    const int SM_NN = 2 * 2 * (2 * 128 * LDA + 2 * 32 * LDN);    // 108544
    cudaFuncSetAttribute(gemm6<false, true>,  cudaFuncAttributeMaxDynamicSharedMemorySize, SM_NN);
    cudaFuncSetAttribute(gemm6<false, false>, cudaFuncAttributeMaxDynamicSharedMemorySize, SM_NN);
    cudaFuncSetAttribute(gemm6<true,  false>, cudaFuncAttributeMaxDynamicSharedMemorySize, SM_T);

    const int M = BATCH * SEQ;          // 8192
    const float scale = 0.125f;         // 1/sqrt(64)
    dim3 b256(256);

    const size_t sQ = (size_t)SEQ * DIM;

    // pre-split inputs (W's stacked q|k|v)
    split_f32<<<(int)(NQ / 4 + 255) / 256, b256>>>(x, xh, xl, (int)(NQ / 4));
    split_f32<<<(int)(NW / 4 + 255) / 256, b256>>>(Wq, W3h,          W3l,          (int)(NW / 4));
    split_f32<<<(int)(NW / 4 + 255) / 256, b256>>>(Wk, W3h + NW,     W3l + NW,     (int)(NW / 4));
    split_f32<<<(int)(NW / 4 + 255) / 256, b256>>>(Wv, W3h + 2 * NW, W3l + 2 * NW, (int)(NW / 4));
    split_f32<<<(int)(NW / 4 + 255) / 256, b256>>>(Wo, Woh, Wol, (int)(NW / 4));

    // fused QKV projection: z selects weight/bias/output slice
    dim3 gProj(DIM / 256, M / 128, 3);
    gemm6<false, true><<<gProj, b256, SM_NN>>>(xh, xl, W3h, W3l, nullptr,
                                               QKVh, QKVl, bq, bk, bv,
                                               DIM, DIM, 1.f, 0, NW, NQ);

    __nv_bfloat16 *Qh = QKVh,          *Ql = QKVl;
    __nv_bfloat16 *Kh = QKVh + NQ,     *Kl = QKVl + NQ;
    __nv_bfloat16 *Vh = QKVh + 2 * NQ, *Vl = QKVl + 2 * NQ;

    // scores: S = scale * Q @ K^T  (z = batch)
    dim3 gScore(SEQ / 256, SEQ / 128, BATCH);
    gemm6<true, false><<<gScore, b256, SM_T>>>(Qh, Ql, Kh, Kl, S, nullptr, nullptr,
                                               nullptr, nullptr, nullptr,
                                               SEQ, DIM, scale,
                                               sQ, sQ, (size_t)SEQ * SEQ);

    softmax_split<<<BATCH * SEQ, b256>>>(S, Ph, Pl);

    // O = P @ V  (z = batch)
    dim3 gPV(DIM / 256, SEQ / 128, BATCH);
    gemm6<false, true><<<gPV, b256, SM_NN>>>(Ph, Pl, Vh, Vl, nullptr, Oh, Ol,
                                             nullptr, nullptr, nullptr,
                                             DIM, SEQ, 1.f,
                                             (size_t)SEQ * SEQ, sQ, sQ);

    // out = O @ Wo + bo
    dim3 gOut(DIM / 256, M / 128, 1);
    gemm6<false, false><<<gOut, b256, SM_NN>>>(Oh, Ol, Woh, Wol, out, nullptr, nullptr,
                                               bo, bo, bo,
                                               DIM, DIM, 1.f, 0, 0, 0);
}

// round 7
// speedup vs baseline: 1.2499x; 1.2379x over previous
#include <cuda_runtime.h>
#include <cuda_fp16.h>
#include <math.h>
#include <stdint.h>

#define BATCH 2
#define SEQ   4096
#define DIM   1024

#define NQ  ((size_t)BATCH * SEQ * DIM)
#define NP  ((size_t)BATCH * SEQ * SEQ)
#define NW  ((size_t)DIM * DIM)

// ---- device scratch (fp16 hi/lo) ----
__device__ __half g_xh[NQ],  g_xl[NQ];
__device__ __half g_W3h[3 * NW], g_W3l[3 * NW];   // Wq|Wk|Wv stacked
__device__ __half g_Woh[NW], g_Wol[NW];
__device__ __half g_QKVh[3 * NQ], g_QKVl[3 * NQ]; // Q|K|V stacked (split)
__device__ __half g_O[NQ];                         // O single fp16
__device__ __half g_P[NP];                         // probs single fp16
__device__ float  g_S[NP];                         // fp32 scores

// ---------------------------------------------------------------------------
// PTX helpers
// ---------------------------------------------------------------------------
__device__ __forceinline__ uint32_t cvta_s(const void* p) {
    return (uint32_t)__cvta_generic_to_shared(p);
}
__device__ __forceinline__ void cp16(uint32_t dst, const void* src) {
    asm volatile("cp.async.cg.shared.global [%0], [%1], 16;" :: "r"(dst), "l"(src));
}
__device__ __forceinline__ void ldmx4(uint32_t* r, uint32_t a) {
    asm volatile("ldmatrix.sync.aligned.m8n8.x4.shared.b16 {%0,%1,%2,%3}, [%4];"
                 : "=r"(r[0]), "=r"(r[1]), "=r"(r[2]), "=r"(r[3]) : "r"(a));
}
__device__ __forceinline__ void ldmx4t(uint32_t* r, uint32_t a) {
    asm volatile("ldmatrix.sync.aligned.m8n8.x4.trans.shared.b16 {%0,%1,%2,%3}, [%4];"
                 : "=r"(r[0]), "=r"(r[1]), "=r"(r[2]), "=r"(r[3]) : "r"(a));
}
__device__ __forceinline__ void mma16816(float* c, const uint32_t* a, const uint32_t* b) {
    asm volatile(
        "mma.sync.aligned.m16n8k16.row.col.f32.f16.f16.f32 "
        "{%0,%1,%2,%3}, {%4,%5,%6,%7}, {%8,%9}, {%0,%1,%2,%3};"
        : "+f"(c[0]), "+f"(c[1]), "+f"(c[2]), "+f"(c[3])
        : "r"(a[0]), "r"(a[1]), "r"(a[2]), "r"(a[3]), "r"(b[0]), "r"(b[1]));
}
__device__ __forceinline__ __half2 hi2(float a, float b) {
    return __floats2half2_rn(a, b);
}
__device__ __forceinline__ __half2 lo2(float a, float b, __half2 h) {
    return __floats2half2_rn(a - __half2float(__low2half(h)),
                             b - __half2float(__high2half(h)));
}

// ---------------------------------------------------------------------------
// Split-fp16 GEMM (R3-proven shape): CTA 128x128, BK=32, 256 thr, warps 2x4,
// warp tile 64x32, 2-stage cp.async.  C = alpha * A @ op(B) + bias[z].
//   SPLIT_A: 3 passes (Ah*Bh, Ah*Bl, Al*Bh). else 2 passes (Ah*Bh, Ah*Bl).
//   OUT: 0 = fp32, 1 = split fp16 hi/lo, 2 = single fp16.
// ---------------------------------------------------------------------------
constexpr int LDA    = 40;   // 32 + 8 pad
constexpr int LDB_NN = 136;  // 128 + 8 pad

template <bool TRANSB, bool SPLIT_A>
__device__ __forceinline__ void load_stage7(
    __half* sb,
    const __half* Ah, const __half* Al,
    const __half* Bh, const __half* Bl,
    int k0, int K, int N, int tid)
{
    constexpr int AE = 128 * LDA;                        // 5120
    constexpr int AT = SPLIT_A ? 2 * AE : AE;
    constexpr int BE = TRANSB ? 128 * LDA : 32 * LDB_NN; // 5120 / 4352
    __half* sAh = sb;
    __half* sAl = sb + AE;
    __half* sBh = sb + AT;
    __half* sBl = sb + AT + BE;

    // A: 128x32 fp16 -> 512 cp16 per matrix, 2 per thread
#pragma unroll
    for (int i = 0; i < 2; i++) {
        int c = tid + (i << 8);
        int row = c >> 2, col = (c & 3) << 3;
        size_t g = (size_t)row * K + k0 + col;
        uint32_t so = row * LDA + col;
        cp16(cvta_s(sAh + so), Ah + g);
        if (SPLIT_A) cp16(cvta_s(sAl + so), Al + g);
    }
    if (TRANSB) {
#pragma unroll
        for (int i = 0; i < 2; i++) {
            int c = tid + (i << 8);
            int row = c >> 2, col = (c & 3) << 3;
            size_t g = (size_t)row * K + k0 + col;
            uint32_t so = row * LDA + col;
            cp16(cvta_s(sBh + so), Bh + g);
            cp16(cvta_s(sBl + so), Bl + g);
        }
    } else {
#pragma unroll
        for (int i = 0; i < 2; i++) {
            int c = tid + (i << 8);
            int row = c >> 4, col = (c & 15) << 3;
            size_t g = (size_t)(k0 + row) * N + col;
            uint32_t so = row * LDB_NN + col;
            cp16(cvta_s(sBh + so), Bh + g);
            cp16(cvta_s(sBl + so), Bl + g);
        }
    }
    asm volatile("cp.async.commit_group;");
}

template <bool TRANSB, bool SPLIT_A, int OUT>
__global__ __launch_bounds__(256, 2)
void gemm7(const __half* __restrict__ Agh, const __half* __restrict__ Agl,
           const __half* __restrict__ Bgh, const __half* __restrict__ Bgl,
           float* __restrict__ Cf,
           __half* __restrict__ Ch, __half* __restrict__ Cl,
           const float* __restrict__ b0, const float* __restrict__ b1,
           const float* __restrict__ b2,
           int N, int K, float alpha,
           size_t sA, size_t sB, size_t sC)
{
    extern __shared__ __align__(16) char smraw[];
    __half* sm = (__half*)smraw;
    constexpr int AE    = 128 * LDA;
    constexpr int AT    = SPLIT_A ? 2 * AE : AE;
    constexpr int BE    = TRANSB ? 128 * LDA : 32 * LDB_NN;
    constexpr int STAGE = AT + 2 * BE;
    constexpr int LDB   = TRANSB ? LDA : LDB_NN;

    const int tid  = threadIdx.x;
    const int lane = tid & 31;
    const int warp = tid >> 5;
    const int wm   = warp & 1;    // 2 row groups of 64
    const int wn   = warp >> 1;   // 4 col groups of 32
    const int z    = blockIdx.z;
    const int bm = blockIdx.y << 7, bn = blockIdx.x << 7;

    const float* bias = (z == 0) ? b0 : (z == 1) ? b1 : b2;

    const __half* Abh = Agh + z * sA + (size_t)bm * K;
    const __half* Abl = SPLIT_A ? (Agl + z * sA + (size_t)bm * K) : nullptr;
    const __half *Bbh, *Bbl;
    if (TRANSB) {
        Bbh = Bgh + z * sB + (size_t)bn * K;
        Bbl = Bgl + z * sB + (size_t)bn * K;
    } else {
        Bbh = Bgh + z * sB + bn;
        Bbl = Bgl + z * sB + bn;
    }

    float acc[4][4][4];
#pragma unroll
    for (int i = 0; i < 4; i++)
#pragma unroll
        for (int j = 0; j < 4; j++)
#pragma unroll
            for (int l = 0; l < 4; l++) acc[i][j][l] = 0.f;

    const int lm_r = lane & 15;
    const int lm_c = (lane >> 4) << 3;
    const int tr_k = (lane & 7) | (((lane >> 3) & 1) << 3);
    const int tr_n = (lane >> 4) << 3;

    load_stage7<TRANSB, SPLIT_A>(sm, Abh, Abl, Bbh, Bbl, 0, K, N, tid);

    const int nT = K >> 5;
    for (int kt = 0; kt < nT; kt++) {
        asm volatile("cp.async.wait_group 0;");
        __syncthreads();
        if (kt + 1 < nT)
            load_stage7<TRANSB, SPLIT_A>(sm + ((kt + 1) & 1) * STAGE,
                                         Abh, Abl, Bbh, Bbl, (kt + 1) << 5, K, N, tid);

        __half* cs  = sm + (kt & 1) * STAGE;
        __half* sAh = cs;
        __half* sAl = cs + AE;
        __half* sBh = cs + AT;
        __half* sBl = cs + AT + BE;

#pragma unroll
        for (int ks = 0; ks < 2; ks++) {
            uint32_t af[4][4], bh[4][2], bl[4][2];

            if (TRANSB) {
#pragma unroll
                for (int h = 0; h < 2; h++) {
                    int row = wn * 32 + h * 16 + lm_r;
                    int col = ks * 16 + lm_c;
                    uint32_t t[4];
                    ldmx4(t, cvta_s(&sBh[row * LDB + col]));
                    bh[2 * h][0] = t[0]; bh[2 * h][1] = t[2];
                    bh[2 * h + 1][0] = t[1]; bh[2 * h + 1][1] = t[3];
                    ldmx4(t, cvta_s(&sBl[row * LDB + col]));
                    bl[2 * h][0] = t[0]; bl[2 * h][1] = t[2];
                    bl[2 * h + 1][0] = t[1]; bl[2 * h + 1][1] = t[3];
                }
            } else {
                int krow = ks * 16 + tr_k;
#pragma unroll
                for (int h = 0; h < 2; h++) {
                    int col = wn * 32 + h * 16 + tr_n;
                    uint32_t t[4];
                    ldmx4t(t, cvta_s(&sBh[krow * LDB + col]));
                    bh[2 * h][0] = t[0]; bh[2 * h][1] = t[1];
                    bh[2 * h + 1][0] = t[2]; bh[2 * h + 1][1] = t[3];
                    ldmx4t(t, cvta_s(&sBl[krow * LDB + col]));
                    bl[2 * h][0] = t[0]; bl[2 * h][1] = t[1];
                    bl[2 * h + 1][0] = t[2]; bl[2 * h + 1][1] = t[3];
                }
            }

            // A hi: Ah*Bh + Ah*Bl
#pragma unroll
            for (int mf = 0; mf < 4; mf++) {
                int row = wm * 64 + mf * 16 + lm_r;
                ldmx4(af[mf], cvta_s(&sAh[row * LDA + ks * 16 + lm_c]));
            }
#pragma unroll
            for (int mf = 0; mf < 4; mf++)
#pragma unroll
                for (int nf = 0; nf < 4; nf++) {
                    mma16816(acc[mf][nf], af[mf], bh[nf]);
                    mma16816(acc[mf][nf], af[mf], bl[nf]);
                }
            if (SPLIT_A) {
                // A lo: Al*Bh
#pragma unroll
                for (int mf = 0; mf < 4; mf++) {
                    int row = wm * 64 + mf * 16 + lm_r;
                    ldmx4(af[mf], cvta_s(&sAl[row * LDA + ks * 16 + lm_c]));
                }
#pragma unroll
                for (int mf = 0; mf < 4; mf++)
#pragma unroll
                    for (int nf = 0; nf < 4; nf++)
                        mma16816(acc[mf][nf], af[mf], bh[nf]);
            }
        }
    }

    // ---- epilogue
    const int g  = lane >> 2;
    const int t2 = (lane & 3) << 1;
#pragma unroll
    for (int mf = 0; mf < 4; mf++) {
        int r0 = wm * 64 + mf * 16 + g;
#pragma unroll
        for (int nf = 0; nf < 4; nf++) {
            int c = wn * 32 + nf * 8 + t2;
            float bb0 = 0.f, bb1 = 0.f;
            if (bias) { bb0 = bias[bn + c]; bb1 = bias[bn + c + 1]; }
            float v00 = acc[mf][nf][0] * alpha + bb0;
            float v01 = acc[mf][nf][1] * alpha + bb1;
            float v10 = acc[mf][nf][2] * alpha + bb0;
            float v11 = acc[mf][nf][3] * alpha + bb1;
            if (OUT == 1) {
                __half* Chb = Ch + z * sC + (size_t)bm * N + bn;
                __half* Clb = Cl + z * sC + (size_t)bm * N + bn;
                __half2 h0 = hi2(v00, v01), h1 = hi2(v10, v11);
                __half2 L0 = lo2(v00, v01, h0), L1 = lo2(v10, v11, h1);
                *(__half2*)(Chb + (size_t)r0 * N + c)       = h0;
                *(__half2*)(Chb + (size_t)(r0 + 8) * N + c) = h1;
                *(__half2*)(Clb + (size_t)r0 * N + c)       = L0;
                *(__half2*)(Clb + (size_t)(r0 + 8) * N + c) = L1;
            } else if (OUT == 2) {
                __half* Chb = Ch + z * sC + (size_t)bm * N + bn;
                *(__half2*)(Chb + (size_t)r0 * N + c)       = hi2(v00, v01);
                *(__half2*)(Chb + (size_t)(r0 + 8) * N + c) = hi2(v10, v11);
            } else {
                float* Cfb = Cf + z * sC + (size_t)bm * N + bn;
                *(float2*)(Cfb + (size_t)r0 * N + c)       = make_float2(v00, v01);
                *(float2*)(Cfb + (size_t)(r0 + 8) * N + c) = make_float2(v10, v11);
            }
        }
    }
}

// ---------------------------------------------------------------------------
// elementwise fp32 -> (fp16 hi, fp16 lo)
// ---------------------------------------------------------------------------
__global__ __launch_bounds__(256)
void split_f32h(const float* __restrict__ x, __half* __restrict__ h,
                __half* __restrict__ l, int n4)
{
    int i = blockIdx.x * blockDim.x + threadIdx.x;
    if (i >= n4) return;
    float4 v = ((const float4*)x)[i];
    __half2 h0 = hi2(v.x, v.y), h1 = hi2(v.z, v.w);
    __half2 l0 = lo2(v.x, v.y, h0), l1 = lo2(v.z, v.w, h1);
    ((__half2*)h)[2 * i]     = h0;
    ((__half2*)h)[2 * i + 1] = h1;
    ((__half2*)l)[2 * i]     = l0;
    ((__half2*)l)[2 * i + 1] = l1;
}

// ---------------------------------------------------------------------------
// Row softmax over 4096 fp32 -> single fp16 probs. 1 block (256 thr) / row.
// ---------------------------------------------------------------------------
__global__ __launch_bounds__(256)
void softmax_h(const float* __restrict__ S, __half* __restrict__ P)
{
    const float* row = S + (size_t)blockIdx.x * SEQ;
    __half* rp = P + (size_t)blockIdx.x * SEQ;
    const int tid = threadIdx.x;

    float v[16];
#pragma unroll
    for (int i = 0; i < 4; i++) {
        float4 t = *(const float4*)(row + i * 1024 + tid * 4);
        v[i * 4 + 0] = t.x; v[i * 4 + 1] = t.y;
        v[i * 4 + 2] = t.z; v[i * 4 + 3] = t.w;
    }
    __shared__ float sh[8];

    float m = -1e30f;
#pragma unroll
    for (int i = 0; i < 16; i++) m = fmaxf(m, v[i]);
#pragma unroll
    for (int o = 16; o > 0; o >>= 1) m = fmaxf(m, __shfl_xor_sync(0xffffffffu, m, o));
    if ((tid & 31) == 0) sh[tid >> 5] = m;
    __syncthreads();
    {
        float t = sh[tid & 7];
#pragma unroll
        for (int o = 4; o > 0; o >>= 1) t = fmaxf(t, __shfl_xor_sync(0xffffffffu, t, o));
        m = t;
    }
    __syncthreads();

    float s = 0.f;
#pragma unroll
    for (int i = 0; i < 16; i++) { v[i] = __expf(v[i] - m); s += v[i]; }
#pragma unroll
    for (int o = 16; o > 0; o >>= 1) s += __shfl_xor_sync(0xffffffffu, s, o);
    if ((tid & 31) == 0) sh[tid >> 5] = s;
    __syncthreads();
    {
        float t = sh[tid & 7];
#pragma unroll
        for (int o = 4; o > 0; o >>= 1) t += __shfl_xor_sync(0xffffffffu, t, o);
        s = t;
    }
    const float inv = 1.f / s;
#pragma unroll
    for (int i = 0; i < 4; i++) {
        int off = i * 1024 + tid * 4;
        *(__half2*)(rp + off)     = hi2(v[i * 4 + 0] * inv, v[i * 4 + 1] * inv);
        *(__half2*)(rp + off + 2) = hi2(v[i * 4 + 2] * inv, v[i * 4 + 3] * inv);
    }
}

// ---------------------------------------------------------------------------
// kernel_launch
// ---------------------------------------------------------------------------
extern "C" void kernel_launch(void* const* d_in, const int* in_sizes, int n_in,
                              void* d_out, int out_size)
{
    const float* x  = (const float*)d_in[0];
    const float* Wq = (const float*)d_in[1];
    const float* bq = (const float*)d_in[2];
    const float* Wk = (const float*)d_in[3];
    const float* bk = (const float*)d_in[4];
    const float* Wv = (const float*)d_in[5];
    const float* bv = (const float*)d_in[6];
    const float* Wo = (const float*)d_in[7];
    const float* bo = (const float*)d_in[8];
    float* out = (float*)d_out;

    __half *xh, *xl, *W3h, *W3l, *Woh, *Wol, *QKVh, *QKVl, *O, *P;
    float* S;
    cudaGetSymbolAddress((void**)&xh, g_xh);     cudaGetSymbolAddress((void**)&xl, g_xl);
    cudaGetSymbolAddress((void**)&W3h, g_W3h);   cudaGetSymbolAddress((void**)&W3l, g_W3l);
    cudaGetSymbolAddress((void**)&Woh, g_Woh);   cudaGetSymbolAddress((void**)&Wol, g_Wol);
    cudaGetSymbolAddress((void**)&QKVh, g_QKVh); cudaGetSymbolAddress((void**)&QKVl, g_QKVl);
    cudaGetSymbolAddress((void**)&O, g_O);       cudaGetSymbolAddress((void**)&P, g_P);
    cudaGetSymbolAddress((void**)&S, g_S);

    // dynamic smem bytes (2 stages, fp16)
    const int SM_PROJ = 2 * 2 * (2 * 128 * LDA + 2 * 32 * LDB_NN);  // 75776
    const int SM_SC   = 2 * 2 * (2 * 128 * LDA + 2 * 128 * LDA);    // 81920
    const int SM_PV   = 2 * 2 * (128 * LDA + 2 * 32 * LDB_NN);      // 55296
    cudaFuncSetAttribute(gemm7<false, true,  1>, cudaFuncAttributeMaxDynamicSharedMemorySize, SM_PROJ);
    cudaFuncSetAttribute(gemm7<true,  true,  0>, cudaFuncAttributeMaxDynamicSharedMemorySize, SM_SC);
    cudaFuncSetAttribute(gemm7<false, false, 2>, cudaFuncAttributeMaxDynamicSharedMemorySize, SM_PV);
    cudaFuncSetAttribute(gemm7<false, false, 0>, cudaFuncAttributeMaxDynamicSharedMemorySize, SM_PV);

    const int M = BATCH * SEQ;          // 8192
    const float scale = 0.125f;         // 1/sqrt(64)
    dim3 b256(256);
    const size_t sQ = (size_t)SEQ * DIM;

    // pre-split inputs
    split_f32h<<<(int)(NQ / 4 + 255) / 256, b256>>>(x, xh, xl, (int)(NQ / 4));
    split_f32h<<<(int)(NW / 4 + 255) / 256, b256>>>(Wq, W3h,          W3l,          (int)(NW / 4));
    split_f32h<<<(int)(NW / 4 + 255) / 256, b256>>>(Wk, W3h + NW,     W3l + NW,     (int)(NW / 4));
    split_f32h<<<(int)(NW / 4 + 255) / 256, b256>>>(Wv, W3h + 2 * NW, W3l + 2 * NW, (int)(NW / 4));
    split_f32h<<<(int)(NW / 4 + 255) / 256, b256>>>(Wo, Woh, Wol, (int)(NW / 4));

    // fused QKV projection (3-pass, split fp16 out)
    dim3 gProj(DIM / 128, M / 128, 3);
    gemm7<false, true, 1><<<gProj, b256, SM_PROJ>>>(xh, xl, W3h, W3l, nullptr,
                                                    QKVh, QKVl, bq, bk, bv,
                                                    DIM, DIM, 1.f, 0, NW, NQ);

    __half *Qh = QKVh,          *Ql = QKVl;
    __half *Kh = QKVh + NQ,     *Kl = QKVl + NQ;
    __half *Vh = QKVh + 2 * NQ, *Vl = QKVl + 2 * NQ;

    // scores: S = scale * Q @ K^T (3-pass, fp32 out)
    dim3 gScore(SEQ / 128, SEQ / 128, BATCH);
    gemm7<true, true, 0><<<gScore, b256, SM_SC>>>(Qh, Ql, Kh, Kl, S, nullptr, nullptr,
                                                  nullptr, nullptr, nullptr,
                                                  SEQ, DIM, scale,
                                                  sQ, sQ, (size_t)SEQ * SEQ);

    // softmax -> single fp16 probs
    softmax_h<<<BATCH * SEQ, b256>>>(S, P);

    // O = P @ V (2-pass: Ph*Vh + Ph*Vl; single fp16 out)
    dim3 gPV(DIM / 128, SEQ / 128, BATCH);
    gemm7<false, false, 2><<<gPV, b256, SM_PV>>>(P, nullptr, Vh, Vl, nullptr,
                                                 O, nullptr,
                                                 nullptr, nullptr, nullptr,
                                                 DIM, SEQ, 1.f,
                                                 (size_t)SEQ * SEQ, sQ, sQ);

    // out = O @ Wo + bo (2-pass: Oh*Wh + Oh*Wl; fp32 out)
    dim3 gOut(DIM / 128, M / 128, 1);
    gemm7<false, false, 0><<<gOut, b256, SM_PV>>>(O, nullptr, Woh, Wol, out,
                                                  nullptr, nullptr,
                                                  bo, bo, bo,
                                                  DIM, DIM, 1.f, 0, 0, 0);
}